// round 7
// baseline (speedup 1.0000x reference)
#include <cuda_runtime.h>
#include <math.h>

// ---------------------------------------------------------------------------
// Problem constants
// ---------------------------------------------------------------------------
#define BB      2
#define SEQ     2048
#define DMODEL  2048
#define NHEAD   16
#define NKV     4
#define DHEAD   128
#define QINNER  (NHEAD * DHEAD)    // 2048
#define KVINNER (NKV * DHEAD)      // 512
#define NREP    (NHEAD / NKV)      // 4
#define MROWS   (BB * SEQ)         // 4096

// Scratch (allocation-free rule: device globals)
__device__ float g_q[MROWS * QINNER];
__device__ float g_k[MROWS * KVINNER];
__device__ float g_v[MROWS * KVINNER];
__device__ float g_att[MROWS * QINNER];

// ---------------------------------------------------------------------------
// tf32 helpers
// ---------------------------------------------------------------------------
__device__ __forceinline__ float f2tf(float x) {
    unsigned y;
    asm("cvt.rna.tf32.f32 %0, %1;" : "=r"(y) : "f"(x));
    return __uint_as_float(y);
}
__device__ __forceinline__ unsigned f2tfu(float x) {
    unsigned y;
    asm("cvt.rna.tf32.f32 %0, %1;" : "=r"(y) : "f"(x));
    return y;
}

// D += A(16x8) * B(8x8), tf32 inputs, fp32 accum
__device__ __forceinline__ void mma8(float* d, const unsigned* a, const unsigned* b) {
    asm("mma.sync.aligned.m16n8k8.row.col.f32.tf32.tf32.f32 "
        "{%0,%1,%2,%3},{%4,%5,%6,%7},{%8,%9},{%0,%1,%2,%3};"
        : "+f"(d[0]), "+f"(d[1]), "+f"(d[2]), "+f"(d[3])
        : "r"(a[0]), "r"(a[1]), "r"(a[2]), "r"(a[3]), "r"(b[0]), "r"(b[1]));
}

// ---------------------------------------------------------------------------
// tf32 GEMM body with fragment-major smem: C = A @ W^T + bias
// 128x128x32 tiles, 8 warps (2 wm x 4 wn), warp = 64x32 via 4x4 m16n8k8.
// A frags: Af[ks(4)][wmSel(2)][mi(4)][lane^ks] uint4 =
//          {A[r][k], A[r+8][k], A[r][k+4], A[r+8][k+4]}, r=wm+mi*16+gID, k=ks*8+tig
// B frags: Bf[ks(4)][wnSel(4)][nip(2)][lane^ks] uint4 =
//          {W[c][k], W[c][k+4], W[c+8][k], W[c+8][k+4]}, c=wn+2nip*8+gID
// ---------------------------------------------------------------------------
#define TBM 128
#define TBN 128
#define TBK 32
#define GF_U4 1024   // per operand: 1024 uint4 = 16KB

__device__ __forceinline__
void gemm_body(const float* __restrict__ A, const float* __restrict__ W,
               const float* __restrict__ bias, float* __restrict__ C,
               int N, int K, int bm, int bn, uint4* Af, uint4* Bf)
{
    const int tid   = threadIdx.x;
    const int lane  = tid & 31;
    const int wid   = tid >> 5;
    const int gID   = lane >> 2;
    const int tig   = lane & 3;
    const int wmSel = wid & 1;
    const int wnSel = wid >> 1;

    float* Aff = (float*)Af;
    float* Bff = (float*)Bf;

    float acc[4][4][4];
#pragma unroll
    for (int mi = 0; mi < 4; mi++)
#pragma unroll
        for (int ni = 0; ni < 4; ni++)
#pragma unroll
            for (int j = 0; j < 4; j++) acc[mi][ni][j] = 0.f;

    for (int k0 = 0; k0 < K; k0 += TBK) {
        // ---- fill fragment-major tiles ----
#pragma unroll
        for (int it = 0; it < 4; it++) {
            int idx  = tid + it * 256;      // 0..1023
            int row  = idx >> 3;            // 0..127
            int c4   = (idx & 7) << 2;      // 0..28
            int ks   = c4 >> 3;
            int half = (c4 >> 2) & 1;
            // A element (row, c4..c4+3)
            {
                float4 va = *(const float4*)(A + (size_t)(bm + row) * K + k0 + c4);
                int au = ((ks * 2 + (row >> 6)) * 4 + ((row >> 4) & 3)) * 32 + (row & 7) * 4;
                int aw = ((row >> 3) & 1) + (half << 1);
                Aff[(au + (0 ^ ks)) * 4 + aw] = f2tf(va.x);
                Aff[(au + (1 ^ ks)) * 4 + aw] = f2tf(va.y);
                Aff[(au + (2 ^ ks)) * 4 + aw] = f2tf(va.z);
                Aff[(au + (3 ^ ks)) * 4 + aw] = f2tf(va.w);
            }
            // B element (row = weight row, c4..c4+3)
            {
                float4 vb = *(const float4*)(W + (size_t)(bn + row) * K + k0 + c4);
                int bu = ((ks * 4 + (row >> 5)) * 2 + ((row >> 4) & 1)) * 32 + (row & 7) * 4;
                int bw = (((row >> 3) & 1) << 1) + half;
                Bff[(bu + (0 ^ ks)) * 4 + bw] = f2tf(vb.x);
                Bff[(bu + (1 ^ ks)) * 4 + bw] = f2tf(vb.y);
                Bff[(bu + (2 ^ ks)) * 4 + bw] = f2tf(vb.z);
                Bff[(bu + (3 ^ ks)) * 4 + bw] = f2tf(vb.w);
            }
        }
        __syncthreads();

        // ---- compute: 4 k-steps, vectorized fragment loads ----
#pragma unroll
        for (int ks = 0; ks < 4; ks++) {
            int lsw = lane ^ ks;
            uint4 af4[4], bf4[2];
#pragma unroll
            for (int mi = 0; mi < 4; mi++)
                af4[mi] = Af[((ks * 2 + wmSel) * 4 + mi) * 32 + lsw];
#pragma unroll
            for (int nip = 0; nip < 2; nip++)
                bf4[nip] = Bf[((ks * 4 + wnSel) * 2 + nip) * 32 + lsw];
#pragma unroll
            for (int mi = 0; mi < 4; mi++) {
#pragma unroll
                for (int nip = 0; nip < 2; nip++) {
                    unsigned bfe[2] = {bf4[nip].x, bf4[nip].y};
                    unsigned bfo[2] = {bf4[nip].z, bf4[nip].w};
                    mma8(acc[mi][2 * nip],     (const unsigned*)&af4[mi], bfe);
                    mma8(acc[mi][2 * nip + 1], (const unsigned*)&af4[mi], bfo);
                }
            }
        }
        __syncthreads();
    }

    const int wm = wmSel * 64;
    const int wn = wnSel * 32;
#pragma unroll
    for (int mi = 0; mi < 4; mi++) {
        int r = bm + wm + mi * 16 + gID;
#pragma unroll
        for (int ni = 0; ni < 4; ni++) {
            int c = bn + wn + ni * 8 + 2 * tig;
            float2 bv = *(const float2*)(bias + c);
            *(float2*)(C + (size_t)r * N + c) =
                make_float2(acc[mi][ni][0] + bv.x, acc[mi][ni][1] + bv.y);
            *(float2*)(C + (size_t)(r + 8) * N + c) =
                make_float2(acc[mi][ni][2] + bv.x, acc[mi][ni][3] + bv.y);
        }
    }
}

// Fused QKV projection: blockIdx.x 0..15 -> Q cols, 16..19 -> K, 20..23 -> V
__global__ __launch_bounds__(256, 2)
void qkv_tf32(const float* __restrict__ x,
              const float* __restrict__ Wq, const float* __restrict__ bq,
              const float* __restrict__ Wk, const float* __restrict__ bk,
              const float* __restrict__ Wv, const float* __restrict__ bv,
              float* __restrict__ qp, float* __restrict__ kp, float* __restrict__ vp)
{
    __shared__ uint4 Af[GF_U4];
    __shared__ uint4 Bf[GF_U4];
    int bx = blockIdx.x;
    const float *W, *bias; float* C; int N, bn;
    if (bx < 16)      { W = Wq; bias = bq; C = qp; N = QINNER;  bn = bx * 128; }
    else if (bx < 20) { W = Wk; bias = bk; C = kp; N = KVINNER; bn = (bx - 16) * 128; }
    else              { W = Wv; bias = bv; C = vp; N = KVINNER; bn = (bx - 20) * 128; }
    gemm_body(x, W, bias, C, N, DMODEL, blockIdx.y * TBM, bn, Af, Bf);
}

__global__ __launch_bounds__(256, 2)
void oproj_tf32(const float* __restrict__ A, const float* __restrict__ Wo,
                const float* __restrict__ bo, float* __restrict__ C)
{
    __shared__ uint4 Af[GF_U4];
    __shared__ uint4 Bf[GF_U4];
    gemm_body(A, Wo, bo, C, DMODEL, QINNER, blockIdx.y * TBM, blockIdx.x * TBN, Af, Bf);
}

// ---------------------------------------------------------------------------
// tf32 flash attention with fragment-major K/V smem (unchanged from R6).
// ---------------------------------------------------------------------------
#define ABQ  128
#define ABK  64
#define PPAD 68
#define KF_U4 (16 * 4 * 32)     // 2048 uint4 = 32KB
#define VF_U4 (8 * 8 * 32)      // 2048 uint4 = 32KB
#define SMEM_ATTN ((KF_U4 + VF_U4) * 16 + ABQ * PPAD * (int)sizeof(float))

__global__ __launch_bounds__(256, 1)
void attn_tf32(const int* __restrict__ mask)
{
    extern __shared__ float sm[];
    uint4* Kf = (uint4*)sm;
    uint4* Vf = Kf + KF_U4;
    float* Kff = (float*)Kf;
    float* Vff = (float*)Vf;
    float* Ps  = (float*)(Vf + VF_U4);   // [128][PPAD]

    const int tid  = threadIdx.x;
    const int lane = tid & 31;
    const int wid  = tid >> 5;
    const int gID  = lane >> 2;
    const int tig  = lane & 3;
    const int q0   = blockIdx.x * ABQ;
    const int bh   = blockIdx.y;
    const int b    = bh >> 4;
    const int h    = bh & 15;
    const int kh   = h >> 2;
    const float scale = 0.08838834764831845f;   // 1/sqrt(128)

    // ---- Q fragments in registers (rows qr0 = q0+16w+gID, qr0+8) ----
    const int qr0 = q0 + wid * 16 + gID;
    const float* qb0 = g_q + (size_t)(b * SEQ + qr0) * QINNER + h * DHEAD;
    const float* qb1 = qb0 + 8 * QINNER;
    unsigned qa[16][4];
#pragma unroll
    for (int ks = 0; ks < 16; ks++) {
        qa[ks][0] = f2tfu(qb0[ks * 8 + tig]);
        qa[ks][1] = f2tfu(qb1[ks * 8 + tig]);
        qa[ks][2] = f2tfu(qb0[ks * 8 + tig + 4]);
        qa[ks][3] = f2tfu(qb1[ks * 8 + tig + 4]);
    }

    float o[16][4];
#pragma unroll
    for (int n = 0; n < 16; n++)
#pragma unroll
        for (int j = 0; j < 4; j++) o[n][j] = 0.f;
    float m0 = -1e30f, m1 = -1e30f, l0 = 0.f, l1 = 0.f;

    const int* mrow0 = mask + (size_t)b * SEQ * SEQ + (size_t)qr0 * SEQ;
    const int* mrow1 = mrow0 + 8 * SEQ;

    float* prow0 = Ps + (wid * 16 + gID) * PPAD;
    float* prow1 = prow0 + 8 * PPAD;

    const int f_ks  = lane >> 1;
    const int f_half = lane & 1;
    const int f_ni  = lane >> 1;
    const int f_nip = lane >> 2;

    for (int k0 = 0; k0 < SEQ; k0 += ABK) {
        __syncthreads();
        // ---- fill K/V fragment-major tiles (tf32-converted) ----
#pragma unroll
        for (int it = 0; it < 8; it++) {
            int r = wid + it * 8;
            size_t goff = (size_t)(b * SEQ + k0 + r) * KVINNER + kh * DHEAD + lane * 4;
            {
                int ni  = r >> 3, gK = r & 7, nip = ni >> 1;
                int kbase = ((f_ks * 4 + nip) * 32) * 4 + f_half + ((ni & 1) << 1);
                int sw = f_ks & 7;
                float4 kv = *(const float4*)(g_k + goff);
                Kff[kbase + (((gK << 2) | 0) ^ sw) * 4] = f2tf(kv.x);
                Kff[kbase + (((gK << 2) | 1) ^ sw) * 4] = f2tf(kv.y);
                Kff[kbase + (((gK << 2) | 2) ^ sw) * 4] = f2tf(kv.z);
                Kff[kbase + (((gK << 2) | 3) ^ sw) * 4] = f2tf(kv.w);
            }
            {
                int ks2 = r >> 3, tigv = r & 3, halfv = (r >> 2) & 1;
                int vbase = ((ks2 * 8 + f_nip) * 32) * 4 + halfv + ((f_ni & 1) << 1);
                int sw = f_nip & 7;
                int g0 = (lane & 1) << 2;
                float4 vv = *(const float4*)(g_v + goff);
                Vff[vbase + ((((g0 | 0) << 2) | tigv) ^ sw) * 4] = f2tf(vv.x);
                Vff[vbase + ((((g0 | 1) << 2) | tigv) ^ sw) * 4] = f2tf(vv.y);
                Vff[vbase + ((((g0 | 2) << 2) | tigv) ^ sw) * 4] = f2tf(vv.z);
                Vff[vbase + ((((g0 | 3) << 2) | tigv) ^ sw) * 4] = f2tf(vv.w);
            }
        }
        __syncthreads();

        // ---- S = Q @ K^T ----
        float s[8][4];
#pragma unroll
        for (int ni = 0; ni < 8; ni++)
#pragma unroll
            for (int j = 0; j < 4; j++) s[ni][j] = 0.f;

#pragma unroll
        for (int ks = 0; ks < 16; ks++) {
            int lsw = lane ^ (ks & 7);
#pragma unroll
            for (int nip = 0; nip < 4; nip++) {
                uint4 kf = Kf[(ks * 4 + nip) * 32 + lsw];
                unsigned bfe[2] = {kf.x, kf.y};
                unsigned bfo[2] = {kf.z, kf.w};
                mma8(s[2 * nip],     qa[ks], bfe);
                mma8(s[2 * nip + 1], qa[ks], bfo);
            }
        }

        // ---- scale + mask + online softmax ----
        float nm0 = m0, nm1 = m1;
#pragma unroll
        for (int ni = 0; ni < 8; ni++) {
            int cc = k0 + ni * 8 + 2 * tig;
            int2 mm0 = *(const int2*)(mrow0 + cc);
            int2 mm1 = *(const int2*)(mrow1 + cc);
            s[ni][0] = mm0.x ? s[ni][0] * scale : -1e30f;
            s[ni][1] = mm0.y ? s[ni][1] * scale : -1e30f;
            s[ni][2] = mm1.x ? s[ni][2] * scale : -1e30f;
            s[ni][3] = mm1.y ? s[ni][3] * scale : -1e30f;
            nm0 = fmaxf(nm0, fmaxf(s[ni][0], s[ni][1]));
            nm1 = fmaxf(nm1, fmaxf(s[ni][2], s[ni][3]));
        }
        nm0 = fmaxf(nm0, __shfl_xor_sync(0xffffffffu, nm0, 1));
        nm0 = fmaxf(nm0, __shfl_xor_sync(0xffffffffu, nm0, 2));
        nm1 = fmaxf(nm1, __shfl_xor_sync(0xffffffffu, nm1, 1));
        nm1 = fmaxf(nm1, __shfl_xor_sync(0xffffffffu, nm1, 2));

        float corr0 = __expf(m0 - nm0);
        float corr1 = __expf(m1 - nm1);
        m0 = nm0; m1 = nm1;

        float rs0 = 0.f, rs1 = 0.f;
#pragma unroll
        for (int ni = 0; ni < 8; ni++) {
            s[ni][0] = (s[ni][0] > -1e29f) ? __expf(s[ni][0] - m0) : 0.f;
            s[ni][1] = (s[ni][1] > -1e29f) ? __expf(s[ni][1] - m0) : 0.f;
            s[ni][2] = (s[ni][2] > -1e29f) ? __expf(s[ni][2] - m1) : 0.f;
            s[ni][3] = (s[ni][3] > -1e29f) ? __expf(s[ni][3] - m1) : 0.f;
            rs0 += s[ni][0] + s[ni][1];
            rs1 += s[ni][2] + s[ni][3];
        }
        rs0 += __shfl_xor_sync(0xffffffffu, rs0, 1);
        rs0 += __shfl_xor_sync(0xffffffffu, rs0, 2);
        rs1 += __shfl_xor_sync(0xffffffffu, rs1, 1);
        rs1 += __shfl_xor_sync(0xffffffffu, rs1, 2);
        l0 = l0 * corr0 + rs0;
        l1 = l1 * corr1 + rs1;

#pragma unroll
        for (int n = 0; n < 16; n++) {
            o[n][0] *= corr0; o[n][1] *= corr0;
            o[n][2] *= corr1; o[n][3] *= corr1;
        }

        // ---- stash P (tf32) in warp-private smem rows ----
#pragma unroll
        for (int ni = 0; ni < 8; ni++) {
            *(float2*)(prow0 + ni * 8 + 2 * tig) = make_float2(f2tf(s[ni][0]), f2tf(s[ni][1]));
            *(float2*)(prow1 + ni * 8 + 2 * tig) = make_float2(f2tf(s[ni][2]), f2tf(s[ni][3]));
        }
        __syncwarp();

        // ---- O += P @ V ----
#pragma unroll
        for (int ks2 = 0; ks2 < 8; ks2++) {
            unsigned pa[4];
            pa[0] = __float_as_uint(prow0[ks2 * 8 + tig]);
            pa[1] = __float_as_uint(prow1[ks2 * 8 + tig]);
            pa[2] = __float_as_uint(prow0[ks2 * 8 + tig + 4]);
            pa[3] = __float_as_uint(prow1[ks2 * 8 + tig + 4]);
#pragma unroll
            for (int nip = 0; nip < 8; nip++) {
                uint4 vf = Vf[(ks2 * 8 + nip) * 32 + (lane ^ nip)];
                unsigned bfe[2] = {vf.x, vf.y};
                unsigned bfo[2] = {vf.z, vf.w};
                mma8(o[2 * nip],     pa, bfe);
                mma8(o[2 * nip + 1], pa, bfo);
            }
        }
    }

    // ---- normalize + store [b,s,h,d] ----
    float inv0 = (l0 > 0.f) ? (1.f / l0) : 0.f;
    float inv1 = (l1 > 0.f) ? (1.f / l1) : 0.f;
    float* ob0 = g_att + (size_t)(b * SEQ + qr0) * QINNER + h * DHEAD;
    float* ob1 = ob0 + 8 * QINNER;
#pragma unroll
    for (int ni = 0; ni < 16; ni++) {
        *(float2*)(ob0 + ni * 8 + 2 * tig) = make_float2(o[ni][0] * inv0, o[ni][1] * inv0);
        *(float2*)(ob1 + ni * 8 + 2 * tig) = make_float2(o[ni][2] * inv1, o[ni][3] * inv1);
    }
}

// ---------------------------------------------------------------------------
// Launch
// ---------------------------------------------------------------------------
extern "C" void kernel_launch(void* const* d_in, const int* in_sizes, int n_in,
                              void* d_out, int out_size)
{
    const float* x    = (const float*)d_in[0];
    const int*   mask = (const int*)  d_in[1];
    const float* Wq   = (const float*)d_in[2];
    const float* bq   = (const float*)d_in[3];
    const float* Wk   = (const float*)d_in[4];
    const float* bk   = (const float*)d_in[5];
    const float* Wv   = (const float*)d_in[6];
    const float* bv   = (const float*)d_in[7];
    const float* Wo   = (const float*)d_in[8];
    const float* bo   = (const float*)d_in[9];
    float* out = (float*)d_out;

    float *q, *k, *v, *att;
    cudaGetSymbolAddress((void**)&q,   g_q);
    cudaGetSymbolAddress((void**)&k,   g_k);
    cudaGetSymbolAddress((void**)&v,   g_v);
    cudaGetSymbolAddress((void**)&att, g_att);

    cudaFuncSetAttribute(attn_tf32, cudaFuncAttributeMaxDynamicSharedMemorySize, SMEM_ATTN);

    dim3 thr(256);
    qkv_tf32<<<dim3(24, MROWS / TBM), thr>>>(x, Wq, bq, Wk, bk, Wv, bv, q, k, v);
    attn_tf32<<<dim3(SEQ / ABQ, BB * NHEAD), thr, SMEM_ATTN>>>(mask);
    oproj_tf32<<<dim3(DMODEL / TBN, MROWS / TBM), thr>>>(att, Wo, bo, out);
}

// round 8
// speedup vs baseline: 1.0928x; 1.0928x over previous
#include <cuda_runtime.h>
#include <math.h>

// ---------------------------------------------------------------------------
// Problem constants
// ---------------------------------------------------------------------------
#define BB      2
#define SEQ     2048
#define DMODEL  2048
#define NHEAD   16
#define NKV     4
#define DHEAD   128
#define QINNER  (NHEAD * DHEAD)    // 2048
#define KVINNER (NKV * DHEAD)      // 512
#define NREP    (NHEAD / NKV)      // 4
#define MROWS   (BB * SEQ)         // 4096

// Scratch (allocation-free rule: device globals)
__device__ float g_q[MROWS * QINNER];
__device__ float g_k[MROWS * KVINNER];
__device__ float g_v[MROWS * KVINNER];
__device__ float g_att[MROWS * QINNER];

// ---------------------------------------------------------------------------
// tf32 helpers
// ---------------------------------------------------------------------------
__device__ __forceinline__ float f2tf(float x) {
    unsigned y;
    asm("cvt.rna.tf32.f32 %0, %1;" : "=r"(y) : "f"(x));
    return __uint_as_float(y);
}
__device__ __forceinline__ unsigned f2tfu(float x) {
    unsigned y;
    asm("cvt.rna.tf32.f32 %0, %1;" : "=r"(y) : "f"(x));
    return y;
}

// D += A(16x8) * B(8x8), tf32 inputs, fp32 accum
__device__ __forceinline__ void mma8(float* d, const unsigned* a, const unsigned* b) {
    asm("mma.sync.aligned.m16n8k8.row.col.f32.tf32.tf32.f32 "
        "{%0,%1,%2,%3},{%4,%5,%6,%7},{%8,%9},{%0,%1,%2,%3};"
        : "+f"(d[0]), "+f"(d[1]), "+f"(d[2]), "+f"(d[3])
        : "r"(a[0]), "r"(a[1]), "r"(a[2]), "r"(a[3]), "r"(b[0]), "r"(b[1]));
}

__device__ __forceinline__ void cp16(unsigned s, const void* g) {
    asm volatile("cp.async.cg.shared.global [%0], [%1], 16;\n" :: "r"(s), "l"(g));
}

// ---------------------------------------------------------------------------
// tf32 GEMM body: C = A @ W^T + bias. R6 padded layout + cp.async 2-stage
// pipeline. Inputs fed to mma as raw fp32 bits (HW tf32 truncation).
// 128x128x32 tiles, 8 warps (2 wm x 4 wn), warp = 64x32 via 4x4 m16n8k8.
// ---------------------------------------------------------------------------
#define TBM 128
#define TBN 128
#define TBK 32
#define TPAD 36    // smem leading dim; 36 % 32 = 4 -> conflict-free frag reads
#define GEMM_SMEM (2 * 2 * TBM * TPAD * 4)   // 73728 bytes

__device__ __forceinline__
void gemm_body(const float* __restrict__ A, const float* __restrict__ W,
               const float* __restrict__ bias, float* __restrict__ C,
               int N, int K, int bm, int bn, float* As, float* Ws)
{
    const int tid   = threadIdx.x;
    const int lane  = tid & 31;
    const int wid   = tid >> 5;
    const int gID   = lane >> 2;
    const int tig   = lane & 3;
    const int wmSel = wid & 1;
    const int wnSel = wid >> 1;
    const unsigned asb = (unsigned)__cvta_generic_to_shared(As);
    const unsigned wsb = (unsigned)__cvta_generic_to_shared(Ws);

    float acc[4][4][4];
#pragma unroll
    for (int mi = 0; mi < 4; mi++)
#pragma unroll
        for (int ni = 0; ni < 4; ni++)
#pragma unroll
            for (int j = 0; j < 4; j++) acc[mi][ni][j] = 0.f;

    const int NT = K / TBK;

    // prefetch tile 0 into buffer 0
#pragma unroll
    for (int it = 0; it < 4; it++) {
        int idx = tid + it * 256, row = idx >> 3, c4 = (idx & 7) << 2;
        cp16(asb + (unsigned)((row * TPAD + c4) << 2), A + (size_t)(bm + row) * K + c4);
        cp16(wsb + (unsigned)((row * TPAD + c4) << 2), W + (size_t)(bn + row) * K + c4);
    }
    asm volatile("cp.async.commit_group;\n");

    for (int kt = 0; kt < NT; kt++) {
        int buf = kt & 1;
        if (kt + 1 < NT) {
            int k0n = (kt + 1) * TBK, bufn = (kt + 1) & 1;
#pragma unroll
            for (int it = 0; it < 4; it++) {
                int idx = tid + it * 256, row = idx >> 3, c4 = (idx & 7) << 2;
                cp16(asb + (unsigned)(((bufn * TBM + row) * TPAD + c4) << 2),
                     A + (size_t)(bm + row) * K + k0n + c4);
                cp16(wsb + (unsigned)(((bufn * TBM + row) * TPAD + c4) << 2),
                     W + (size_t)(bn + row) * K + k0n + c4);
            }
            asm volatile("cp.async.commit_group;\n");
            asm volatile("cp.async.wait_group 1;\n");
        } else {
            asm volatile("cp.async.wait_group 0;\n");
        }
        __syncthreads();

        const float* Ab = As + buf * TBM * TPAD;
        const float* Wb = Ws + buf * TBM * TPAD;
#pragma unroll
        for (int ks = 0; ks < 4; ks++) {
            unsigned af[4][4], bf[4][2];
#pragma unroll
            for (int mi = 0; mi < 4; mi++) {
                int r = wmSel * 64 + mi * 16 + gID;
                af[mi][0] = __float_as_uint(Ab[r * TPAD + ks * 8 + tig]);
                af[mi][1] = __float_as_uint(Ab[(r + 8) * TPAD + ks * 8 + tig]);
                af[mi][2] = __float_as_uint(Ab[r * TPAD + ks * 8 + tig + 4]);
                af[mi][3] = __float_as_uint(Ab[(r + 8) * TPAD + ks * 8 + tig + 4]);
            }
#pragma unroll
            for (int ni = 0; ni < 4; ni++) {
                int c = wnSel * 32 + ni * 8 + gID;
                bf[ni][0] = __float_as_uint(Wb[c * TPAD + ks * 8 + tig]);
                bf[ni][1] = __float_as_uint(Wb[c * TPAD + ks * 8 + tig + 4]);
            }
#pragma unroll
            for (int mi = 0; mi < 4; mi++)
#pragma unroll
                for (int ni = 0; ni < 4; ni++)
                    mma8(acc[mi][ni], af[mi], bf[ni]);
        }
        __syncthreads();
    }

    const int wm = wmSel * 64;
    const int wn = wnSel * 32;
#pragma unroll
    for (int mi = 0; mi < 4; mi++) {
        int r = bm + wm + mi * 16 + gID;
#pragma unroll
        for (int ni = 0; ni < 4; ni++) {
            int c = bn + wn + ni * 8 + 2 * tig;
            float2 bv = *(const float2*)(bias + c);
            *(float2*)(C + (size_t)r * N + c) =
                make_float2(acc[mi][ni][0] + bv.x, acc[mi][ni][1] + bv.y);
            *(float2*)(C + (size_t)(r + 8) * N + c) =
                make_float2(acc[mi][ni][2] + bv.x, acc[mi][ni][3] + bv.y);
        }
    }
}

// Fused QKV projection: blockIdx.x 0..15 -> Q cols, 16..19 -> K, 20..23 -> V
__global__ __launch_bounds__(256, 2)
void qkv_tf32(const float* __restrict__ x,
              const float* __restrict__ Wq, const float* __restrict__ bq,
              const float* __restrict__ Wk, const float* __restrict__ bk,
              const float* __restrict__ Wv, const float* __restrict__ bv,
              float* __restrict__ qp, float* __restrict__ kp, float* __restrict__ vp)
{
    extern __shared__ float dsm[];
    float* As = dsm;
    float* Ws = dsm + 2 * TBM * TPAD;
    int bx = blockIdx.x;
    const float *W, *bias; float* C; int N, bn;
    if (bx < 16)      { W = Wq; bias = bq; C = qp; N = QINNER;  bn = bx * 128; }
    else if (bx < 20) { W = Wk; bias = bk; C = kp; N = KVINNER; bn = (bx - 16) * 128; }
    else              { W = Wv; bias = bv; C = vp; N = KVINNER; bn = (bx - 20) * 128; }
    gemm_body(x, W, bias, C, N, DMODEL, blockIdx.y * TBM, bn, As, Ws);
}

__global__ __launch_bounds__(256, 2)
void oproj_tf32(const float* __restrict__ A, const float* __restrict__ Wo,
                const float* __restrict__ bo, float* __restrict__ C)
{
    extern __shared__ float dsm[];
    float* As = dsm;
    float* Ws = dsm + 2 * TBM * TPAD;
    gemm_body(A, Wo, bo, C, DMODEL, QINNER, blockIdx.y * TBM, blockIdx.x * TBN, As, Ws);
}

// ---------------------------------------------------------------------------
// tf32 flash attention with fragment-major K/V smem (unchanged from R6).
// ---------------------------------------------------------------------------
#define ABQ  128
#define ABK  64
#define PPAD 68
#define KF_U4 (16 * 4 * 32)     // 2048 uint4 = 32KB
#define VF_U4 (8 * 8 * 32)      // 2048 uint4 = 32KB
#define SMEM_ATTN ((KF_U4 + VF_U4) * 16 + ABQ * PPAD * (int)sizeof(float))

__global__ __launch_bounds__(256, 1)
void attn_tf32(const int* __restrict__ mask)
{
    extern __shared__ float sm[];
    uint4* Kf = (uint4*)sm;
    uint4* Vf = Kf + KF_U4;
    float* Kff = (float*)Kf;
    float* Vff = (float*)Vf;
    float* Ps  = (float*)(Vf + VF_U4);   // [128][PPAD]

    const int tid  = threadIdx.x;
    const int lane = tid & 31;
    const int wid  = tid >> 5;
    const int gID  = lane >> 2;
    const int tig  = lane & 3;
    const int q0   = blockIdx.x * ABQ;
    const int bh   = blockIdx.y;
    const int b    = bh >> 4;
    const int h    = bh & 15;
    const int kh   = h >> 2;
    const float scale = 0.08838834764831845f;   // 1/sqrt(128)

    // ---- Q fragments in registers (rows qr0 = q0+16w+gID, qr0+8) ----
    const int qr0 = q0 + wid * 16 + gID;
    const float* qb0 = g_q + (size_t)(b * SEQ + qr0) * QINNER + h * DHEAD;
    const float* qb1 = qb0 + 8 * QINNER;
    unsigned qa[16][4];
#pragma unroll
    for (int ks = 0; ks < 16; ks++) {
        qa[ks][0] = f2tfu(qb0[ks * 8 + tig]);
        qa[ks][1] = f2tfu(qb1[ks * 8 + tig]);
        qa[ks][2] = f2tfu(qb0[ks * 8 + tig + 4]);
        qa[ks][3] = f2tfu(qb1[ks * 8 + tig + 4]);
    }

    float o[16][4];
#pragma unroll
    for (int n = 0; n < 16; n++)
#pragma unroll
        for (int j = 0; j < 4; j++) o[n][j] = 0.f;
    float m0 = -1e30f, m1 = -1e30f, l0 = 0.f, l1 = 0.f;

    const int* mrow0 = mask + (size_t)b * SEQ * SEQ + (size_t)qr0 * SEQ;
    const int* mrow1 = mrow0 + 8 * SEQ;

    float* prow0 = Ps + (wid * 16 + gID) * PPAD;
    float* prow1 = prow0 + 8 * PPAD;

    const int f_ks  = lane >> 1;
    const int f_half = lane & 1;
    const int f_ni  = lane >> 1;
    const int f_nip = lane >> 2;

    for (int k0 = 0; k0 < SEQ; k0 += ABK) {
        __syncthreads();
        // ---- fill K/V fragment-major tiles (tf32-converted) ----
#pragma unroll
        for (int it = 0; it < 8; it++) {
            int r = wid + it * 8;
            size_t goff = (size_t)(b * SEQ + k0 + r) * KVINNER + kh * DHEAD + lane * 4;
            {
                int ni  = r >> 3, gK = r & 7, nip = ni >> 1;
                int kbase = ((f_ks * 4 + nip) * 32) * 4 + f_half + ((ni & 1) << 1);
                int sw = f_ks & 7;
                float4 kv = *(const float4*)(g_k + goff);
                Kff[kbase + (((gK << 2) | 0) ^ sw) * 4] = f2tf(kv.x);
                Kff[kbase + (((gK << 2) | 1) ^ sw) * 4] = f2tf(kv.y);
                Kff[kbase + (((gK << 2) | 2) ^ sw) * 4] = f2tf(kv.z);
                Kff[kbase + (((gK << 2) | 3) ^ sw) * 4] = f2tf(kv.w);
            }
            {
                int ks2 = r >> 3, tigv = r & 3, halfv = (r >> 2) & 1;
                int vbase = ((ks2 * 8 + f_nip) * 32) * 4 + halfv + ((f_ni & 1) << 1);
                int sw = f_nip & 7;
                int g0 = (lane & 1) << 2;
                float4 vv = *(const float4*)(g_v + goff);
                Vff[vbase + ((((g0 | 0) << 2) | tigv) ^ sw) * 4] = f2tf(vv.x);
                Vff[vbase + ((((g0 | 1) << 2) | tigv) ^ sw) * 4] = f2tf(vv.y);
                Vff[vbase + ((((g0 | 2) << 2) | tigv) ^ sw) * 4] = f2tf(vv.z);
                Vff[vbase + ((((g0 | 3) << 2) | tigv) ^ sw) * 4] = f2tf(vv.w);
            }
        }
        __syncthreads();

        // ---- S = Q @ K^T ----
        float s[8][4];
#pragma unroll
        for (int ni = 0; ni < 8; ni++)
#pragma unroll
            for (int j = 0; j < 4; j++) s[ni][j] = 0.f;

#pragma unroll
        for (int ks = 0; ks < 16; ks++) {
            int lsw = lane ^ (ks & 7);
#pragma unroll
            for (int nip = 0; nip < 4; nip++) {
                uint4 kf = Kf[(ks * 4 + nip) * 32 + lsw];
                unsigned bfe[2] = {kf.x, kf.y};
                unsigned bfo[2] = {kf.z, kf.w};
                mma8(s[2 * nip],     qa[ks], bfe);
                mma8(s[2 * nip + 1], qa[ks], bfo);
            }
        }

        // ---- scale + mask + online softmax ----
        float nm0 = m0, nm1 = m1;
#pragma unroll
        for (int ni = 0; ni < 8; ni++) {
            int cc = k0 + ni * 8 + 2 * tig;
            int2 mm0 = *(const int2*)(mrow0 + cc);
            int2 mm1 = *(const int2*)(mrow1 + cc);
            s[ni][0] = mm0.x ? s[ni][0] * scale : -1e30f;
            s[ni][1] = mm0.y ? s[ni][1] * scale : -1e30f;
            s[ni][2] = mm1.x ? s[ni][2] * scale : -1e30f;
            s[ni][3] = mm1.y ? s[ni][3] * scale : -1e30f;
            nm0 = fmaxf(nm0, fmaxf(s[ni][0], s[ni][1]));
            nm1 = fmaxf(nm1, fmaxf(s[ni][2], s[ni][3]));
        }
        nm0 = fmaxf(nm0, __shfl_xor_sync(0xffffffffu, nm0, 1));
        nm0 = fmaxf(nm0, __shfl_xor_sync(0xffffffffu, nm0, 2));
        nm1 = fmaxf(nm1, __shfl_xor_sync(0xffffffffu, nm1, 1));
        nm1 = fmaxf(nm1, __shfl_xor_sync(0xffffffffu, nm1, 2));

        float corr0 = __expf(m0 - nm0);
        float corr1 = __expf(m1 - nm1);
        m0 = nm0; m1 = nm1;

        float rs0 = 0.f, rs1 = 0.f;
#pragma unroll
        for (int ni = 0; ni < 8; ni++) {
            s[ni][0] = (s[ni][0] > -1e29f) ? __expf(s[ni][0] - m0) : 0.f;
            s[ni][1] = (s[ni][1] > -1e29f) ? __expf(s[ni][1] - m0) : 0.f;
            s[ni][2] = (s[ni][2] > -1e29f) ? __expf(s[ni][2] - m1) : 0.f;
            s[ni][3] = (s[ni][3] > -1e29f) ? __expf(s[ni][3] - m1) : 0.f;
            rs0 += s[ni][0] + s[ni][1];
            rs1 += s[ni][2] + s[ni][3];
        }
        rs0 += __shfl_xor_sync(0xffffffffu, rs0, 1);
        rs0 += __shfl_xor_sync(0xffffffffu, rs0, 2);
        rs1 += __shfl_xor_sync(0xffffffffu, rs1, 1);
        rs1 += __shfl_xor_sync(0xffffffffu, rs1, 2);
        l0 = l0 * corr0 + rs0;
        l1 = l1 * corr1 + rs1;

#pragma unroll
        for (int n = 0; n < 16; n++) {
            o[n][0] *= corr0; o[n][1] *= corr0;
            o[n][2] *= corr1; o[n][3] *= corr1;
        }

        // ---- stash P (tf32) in warp-private smem rows ----
#pragma unroll
        for (int ni = 0; ni < 8; ni++) {
            *(float2*)(prow0 + ni * 8 + 2 * tig) = make_float2(f2tf(s[ni][0]), f2tf(s[ni][1]));
            *(float2*)(prow1 + ni * 8 + 2 * tig) = make_float2(f2tf(s[ni][2]), f2tf(s[ni][3]));
        }
        __syncwarp();

        // ---- O += P @ V ----
#pragma unroll
        for (int ks2 = 0; ks2 < 8; ks2++) {
            unsigned pa[4];
            pa[0] = __float_as_uint(prow0[ks2 * 8 + tig]);
            pa[1] = __float_as_uint(prow1[ks2 * 8 + tig]);
            pa[2] = __float_as_uint(prow0[ks2 * 8 + tig + 4]);
            pa[3] = __float_as_uint(prow1[ks2 * 8 + tig + 4]);
#pragma unroll
            for (int nip = 0; nip < 8; nip++) {
                uint4 vf = Vf[(ks2 * 8 + nip) * 32 + (lane ^ nip)];
                unsigned bfe[2] = {vf.x, vf.y};
                unsigned bfo[2] = {vf.z, vf.w};
                mma8(o[2 * nip],     pa, bfe);
                mma8(o[2 * nip + 1], pa, bfo);
            }
        }
    }

    // ---- normalize + store [b,s,h,d] ----
    float inv0 = (l0 > 0.f) ? (1.f / l0) : 0.f;
    float inv1 = (l1 > 0.f) ? (1.f / l1) : 0.f;
    float* ob0 = g_att + (size_t)(b * SEQ + qr0) * QINNER + h * DHEAD;
    float* ob1 = ob0 + 8 * QINNER;
#pragma unroll
    for (int ni = 0; ni < 16; ni++) {
        *(float2*)(ob0 + ni * 8 + 2 * tig) = make_float2(o[ni][0] * inv0, o[ni][1] * inv0);
        *(float2*)(ob1 + ni * 8 + 2 * tig) = make_float2(o[ni][2] * inv1, o[ni][3] * inv1);
    }
}

// ---------------------------------------------------------------------------
// Launch
// ---------------------------------------------------------------------------
extern "C" void kernel_launch(void* const* d_in, const int* in_sizes, int n_in,
                              void* d_out, int out_size)
{
    const float* x    = (const float*)d_in[0];
    const int*   mask = (const int*)  d_in[1];
    const float* Wq   = (const float*)d_in[2];
    const float* bq   = (const float*)d_in[3];
    const float* Wk   = (const float*)d_in[4];
    const float* bk   = (const float*)d_in[5];
    const float* Wv   = (const float*)d_in[6];
    const float* bv   = (const float*)d_in[7];
    const float* Wo   = (const float*)d_in[8];
    const float* bo   = (const float*)d_in[9];
    float* out = (float*)d_out;

    float *q, *k, *v, *att;
    cudaGetSymbolAddress((void**)&q,   g_q);
    cudaGetSymbolAddress((void**)&k,   g_k);
    cudaGetSymbolAddress((void**)&v,   g_v);
    cudaGetSymbolAddress((void**)&att, g_att);

    cudaFuncSetAttribute(attn_tf32,  cudaFuncAttributeMaxDynamicSharedMemorySize, SMEM_ATTN);
    cudaFuncSetAttribute(qkv_tf32,   cudaFuncAttributeMaxDynamicSharedMemorySize, GEMM_SMEM);
    cudaFuncSetAttribute(oproj_tf32, cudaFuncAttributeMaxDynamicSharedMemorySize, GEMM_SMEM);

    dim3 thr(256);
    qkv_tf32<<<dim3(24, MROWS / TBM), thr, GEMM_SMEM>>>(x, Wq, bq, Wk, bk, Wv, bv, q, k, v);
    attn_tf32<<<dim3(SEQ / ABQ, BB * NHEAD), thr, SMEM_ATTN>>>(mask);
    oproj_tf32<<<dim3(DMODEL / TBN, MROWS / TBM), thr, GEMM_SMEM>>>(att, Wo, bo, out);
}